// round 12
// baseline (speedup 1.0000x reference)
#include <cuda_runtime.h>
#include <cuda_fp16.h>
#include <cstdint>

#define DEV static __device__ __forceinline__

namespace {
constexpr int Mdim = 8192;   // B*S (rows of x)
constexpr int Ndim = 4096;   // out features
constexpr int Kdim = 4096;   // in features
// GEMM computes D[n][m] = sum_k W[k][n] * x[m][k]  (A = W^T sparse 2:4, B = x)
constexpr int BN = 128;      // n-rows per CTA (A side)
constexpr int BMT = 128;     // m-cols per CTA (B side)
constexpr int BK = 64;       // original-k per iteration (2 x k32 mma.sp steps)
constexpr int NTHREADS = 256;
constexpr int STAGES = 4;
constexpr int KTILES = Kdim / BK;              // 64
constexpr int WC_STAGE = BN * 32 * 2;          // compressed A tile: 128 x 32 halves = 8192 B
constexpr int X_STAGE = BMT * BK * 2;          // 128 x 64 halves = 16384 B
constexpr int STAGE_BYTES = 25600;             // 8192+16384+1024 rounded to 1KB mult
constexpr int DYN_SMEM = STAGES * STAGE_BYTES + 1024;  // 103424
constexpr int EPI_PITCH = 132;                 // floats (128 + 4 pad)
constexpr int OV_SEGS = 8;                     // k segments of 512 for overflow slots
constexpr int OV_SLOTS = 5;                    // per segment
}

// ---- device scratch (allocation-free) ----
__device__ __align__(1024) __half g_A[(size_t)Mdim * Kdim];        // x fp16 [m][k]
__device__ __align__(1024) __half g_AT[(size_t)Kdim * Mdim];       // x^T fp16 [k][m]
__device__ __align__(1024) __half g_Wc[(size_t)Ndim * (Kdim / 2)]; // compressed W^T [n][kc]
// metadata: 4 nibbles (4 k-groups) per (k16chunk, n) entry
__device__ __align__(1024) uint16_t g_meta16[(size_t)(Kdim / 16) * Ndim];
__device__ __align__(16) float2 g_ove[(size_t)Ndim * OV_SEGS * OV_SLOTS]; // overflow (w, k)
__device__ __align__(8) unsigned long long g_ovc[Ndim];            // 8 packed u8 counts per n

// ---------------- PTX helpers ----------------

DEV uint32_t smem_u32(const void* p) {
    uint32_t a;
    asm("{ .reg .u64 t; cvta.to.shared.u64 t, %1; cvt.u32.u64 %0, t; }"
        : "=r"(a) : "l"(p));
    return a;
}

DEV void cpasync16(uint32_t dst, const void* src) {
    asm volatile("cp.async.cg.shared.global [%0], [%1], 16;\n" :: "r"(dst), "l"(src));
}

#define CP_COMMIT() asm volatile("cp.async.commit_group;" ::: "memory")
#define CP_WAIT(N)  asm volatile("cp.async.wait_group %0;" :: "n"(N) : "memory")

DEV void ldsm_x4(uint32_t& r0, uint32_t& r1, uint32_t& r2, uint32_t& r3,
                 uint32_t addr) {
    asm volatile("ldmatrix.sync.aligned.m8n8.x4.shared.b16 {%0,%1,%2,%3}, [%4];"
                 : "=r"(r0), "=r"(r1), "=r"(r2), "=r"(r3) : "r"(addr));
}

DEV uint32_t lds16(uint32_t a) {
    uint32_t v;
    asm volatile("ld.shared.u16 %0, [%1];" : "=r"(v) : "r"(a));
    return v;
}

// sparse 2:4 MMA: D[16n x 8m] += A(16x32, 2:4 compressed) * B(32x8), f16 in / f32 acc
DEV void mma_sp(float* d, const uint32_t* a,
                uint32_t b0, uint32_t b1, uint32_t b2, uint32_t b3, uint32_t e) {
    asm volatile(
        "mma.sp::ordered_metadata.sync.aligned.m16n8k32.row.col.f32.f16.f16.f32 "
        "{%0,%1,%2,%3}, {%4,%5,%6,%7}, {%8,%9,%10,%11}, {%0,%1,%2,%3}, %12, 0x0;"
        : "+f"(d[0]), "+f"(d[1]), "+f"(d[2]), "+f"(d[3])
        : "r"(a[0]), "r"(a[1]), "r"(a[2]), "r"(a[3]),
          "r"(b0), "r"(b1), "r"(b2), "r"(b3), "r"(e));
}

// ---------------- converters ----------------

// x -> g_A [m][k] f16 and g_AT [k][m] f16 (32x32 tile transpose)
__global__ void conv_x_dual(const float* __restrict__ x) {
    __shared__ float t[32][33];
    int k0 = blockIdx.x * 32, m0 = blockIdx.y * 32;
    int tx = threadIdx.x, ty = threadIdx.y;  // (32, 8)
#pragma unroll
    for (int j = 0; j < 32; j += 8) {
        float v = x[(size_t)(m0 + ty + j) * Kdim + k0 + tx];
        t[ty + j][tx] = v;
        g_A[(size_t)(m0 + ty + j) * Kdim + k0 + tx] = __float2half_rn(v);
    }
    __syncthreads();
#pragma unroll
    for (int j = 0; j < 32; j += 8)
        g_AT[(size_t)(k0 + ty + j) * Mdim + m0 + tx] = __float2half_rn(t[tx][ty + j]);
}

// Pass 1: 2:4 compress (keep first 2 nnz per group) + per-k16 metadata (4 nibbles)
__global__ void conv_w_sp(const float* __restrict__ W) {
    int n = blockIdx.x * 256 + threadIdx.x;
    int chunk = blockIdx.y;  // k32 chunk, 0..127
    uint32_t meta = 0;       // 8 nibbles, group g at bits [4g, 4g+4)
    __half2 vals[8];
#pragma unroll
    for (int g = 0; g < 8; g++) {
        int base = chunk * 32 + g * 4;
        float v[4];
#pragma unroll
        for (int i = 0; i < 4; i++) v[i] = W[(size_t)(base + i) * Ndim + n];
        int i0 = -1, i1 = -1;
#pragma unroll
        for (int i = 0; i < 4; i++) {
            if (v[i] != 0.0f) {
                if (i0 < 0) i0 = i;
                else if (i1 < 0) i1 = i;
            }
        }
        if (i0 < 0) { i0 = 0; i1 = 1; }
        else if (i1 < 0) { if (i0 == 3) { i0 = 2; i1 = 3; } else i1 = 3; }
        meta |= (uint32_t)(i0 | (i1 << 2)) << (4 * g);
        vals[g] = __floats2half2_rn(v[i0], v[i1]);
    }
    __half* dst = g_Wc + (size_t)n * (Kdim / 2) + chunk * 16;
    reinterpret_cast<uint4*>(dst)[0] = reinterpret_cast<uint4*>(vals)[0];
    reinterpret_cast<uint4*>(dst)[1] = reinterpret_cast<uint4*>(vals)[1];
    // split by k16 half: groups 0-3 -> k16chunk 2*chunk, groups 4-7 -> 2*chunk+1
    g_meta16[(size_t)(2 * chunk) * Ndim + n] = (uint16_t)(meta & 0xFFFF);
    g_meta16[(size_t)(2 * chunk + 1) * Ndim + n] = (uint16_t)(meta >> 16);
}

// Pass 2: deterministic overflow extraction (3rd+ nonzero per group -> slots)
__global__ void conv_w_ov(const float* __restrict__ W) {
    int n = blockIdx.x * 256 + threadIdx.x;
    int seg = blockIdx.y;  // 0..7, 512 k each
    int cnt = 0;
    for (int k0 = seg * 512; k0 < seg * 512 + 512; k0 += 4) {
        int nz = 0;
#pragma unroll
        for (int i = 0; i < 4; i++) {
            float v = W[(size_t)(k0 + i) * Ndim + n];
            if (v != 0.0f) {
                nz++;
                if (nz > 2 && cnt < OV_SLOTS) {
                    g_ove[((size_t)n * OV_SEGS + seg) * OV_SLOTS + cnt] =
                        make_float2(v, __int_as_float(k0 + i));
                    cnt++;
                }
            }
        }
    }
    reinterpret_cast<unsigned char*>(g_ovc)[n * 8 + seg] = (unsigned char)cnt;
}

// ---------------- sparse GEMM ----------------

// smem layouts per stage:
//  sWc: 128 rows x 64B; rows paired to 128B lines: phys chunk = ((r&1)*4 + c) ^ ((r>>1)&7)
//  sX:  128 rows x 128B; phys chunk = c ^ (r&7)
//  sMeta: [4 k16chunks][128 rows] u16 = 1024 B
DEV void load_stage(uint32_t ub, int stage, int kt, int n0, int m0) {
    const int tid = threadIdx.x;
    const uint32_t sW = ub + stage * STAGE_BYTES;
    const uint32_t sX = sW + WC_STAGE;
    const uint32_t sM = sX + X_STAGE;
#pragma unroll
    for (int i = 0; i < 2; i++) {  // Wc: 512 16B chunks
        int idx = tid + i * NTHREADS;
        int r = idx >> 2, c = idx & 3;
        const char* src = (const char*)(g_Wc + (size_t)(n0 + r) * (Kdim / 2) + kt * 32) + c * 16;
        uint32_t ph = (uint32_t)((((r & 1) << 2) | c) ^ ((r >> 1) & 7));
        cpasync16(sW + (r >> 1) * 128 + (ph << 4), src);
    }
#pragma unroll
    for (int i = 0; i < 4; i++) {  // X: 1024 16B chunks
        int idx = tid + i * NTHREADS;
        int r = idx >> 3, c = idx & 7;
        const char* src = (const char*)(g_A + (size_t)(m0 + r) * Kdim + kt * 64) + c * 16;
        cpasync16(sX + r * 128 + ((c ^ (r & 7)) << 4), src);
    }
    if (tid < 64) {  // meta: 4 k16chunks x 128 u16 = 4 x 256B
        int c = tid >> 4, o = tid & 15;  // o: 16B = 8 u16 rows
        cpasync16(sM + c * 256 + o * 16,
                  (const char*)(g_meta16 + (size_t)(kt * 4 + c) * Ndim + n0) + o * 16);
    }
    CP_COMMIT();
}

__global__ void __launch_bounds__(NTHREADS, 2)
gemm_sp_kernel(const float* __restrict__ bias, float* __restrict__ out) {
    extern __shared__ char dynsmem[];
    __shared__ unsigned long long cnts[BN];
    __shared__ float bs[BN];
    const uint32_t raw = smem_u32(dynsmem);
    const uint32_t ub = (raw + 1023u) & ~1023u;

    const int tid = threadIdx.x;
    const int wid = tid >> 5;
    const int lane = tid & 31;
    const int n0 = blockIdx.x * BN;   // A-side (out features)
    const int m0 = blockIdx.y * BMT;  // B-side (tokens)
    const int wn = (wid & 1) * 64;    // warp grid: 2(n) x 4(m); warp tile 64n x 32m
    const int wm = (wid >> 1) * 32;

    if (tid < BN) {
        bs[tid] = bias[n0 + tid];
        cnts[tid] = g_ovc[n0 + tid];
    }

    float acc[4][4][4];
#pragma unroll
    for (int nt = 0; nt < 4; nt++)
#pragma unroll
        for (int mt = 0; mt < 4; mt++)
#pragma unroll
            for (int r = 0; r < 4; r++) acc[nt][mt][r] = 0.0f;

#pragma unroll
    for (int kt = 0; kt < STAGES - 1; kt++) load_stage(ub, kt, kt, n0, m0);

    // lane addressing
    const int a_r = (lane & 15);          // + nt*16 + wn
    const int a_chi = lane >> 4;          // 16B-half of compressed k32 (16 halves)
    const int b_r = ((lane >> 4) << 3) + (lane & 7);  // + mg*16 + wm
    const int b_chi = (lane >> 3) & 1;
    // metadata (selector 0): T(4i+h), h=0 -> k-cols 0-15, h=1 -> 16-31 of the k32 step;
    // word = meta16[row i] | meta16[row i+8] << 16, i = lane>>2.
    const int e_half = lane & 1;          // k16 half within k32 (h=2,3 ignored; use h&1)
    const int e_row = lane >> 2;

    for (int kt = 0; kt < KTILES; kt++) {
        CP_WAIT(2);
        __syncthreads();

        const uint32_t sW = ub + (kt % STAGES) * STAGE_BYTES;
        const uint32_t sX = sW + WC_STAGE;
        const uint32_t sM = sX + X_STAGE;

        {
            const int lt = kt + STAGES - 1;
            if (lt < KTILES) load_stage(ub, lt % STAGES, lt, n0, m0);
            else CP_COMMIT();
        }

#pragma unroll
        for (int s = 0; s < 2; s++) {
            uint32_t a[4][4], e[4], bb[2][2][4];
#pragma unroll
            for (int nt = 0; nt < 4; nt++) {
                int R = wn + nt * 16 + a_r;
                int ch = s * 2 + a_chi;
                uint32_t ph = (uint32_t)((((R & 1) << 2) | ch) ^ ((R >> 1) & 7));
                ldsm_x4(a[nt][0], a[nt][1], a[nt][2], a[nt][3],
                        sW + (R >> 1) * 128 + (ph << 4));
                int mc = s * 2 + e_half;
                int Rm = wn + nt * 16 + e_row;
                uint32_t lo = lds16(sM + mc * 256 + Rm * 2);
                uint32_t hi = lds16(sM + mc * 256 + (Rm + 8) * 2);
                e[nt] = lo | (hi << 16);
            }
#pragma unroll
            for (int mg = 0; mg < 2; mg++)
#pragma unroll
                for (int h = 0; h < 2; h++) {
                    int R = wm + mg * 16 + b_r;
                    int ch = s * 4 + h * 2 + b_chi;
                    ldsm_x4(bb[mg][h][0], bb[mg][h][1], bb[mg][h][2], bb[mg][h][3],
                            sX + R * 128 + ((ch ^ (R & 7)) << 4));
                }
#pragma unroll
            for (int nt = 0; nt < 4; nt++)
#pragma unroll
                for (int mg = 0; mg < 2; mg++)
#pragma unroll
                    for (int u = 0; u < 2; u++)
                        mma_sp(acc[nt][mg * 2 + u], a[nt],
                               bb[mg][0][2 * u], bb[mg][0][2 * u + 1],
                               bb[mg][1][2 * u], bb[mg][1][2 * u + 1], e[nt]);
        }
    }

    CP_WAIT(0);
    __syncthreads();

    // Epilogue: D[n][m] frags -> smem sd[m][n] -> fixup -> coalesced out + bias
    float* sd = reinterpret_cast<float*>(dynsmem + (ub - raw));
#pragma unroll
    for (int nt = 0; nt < 4; nt++)
#pragma unroll
        for (int mt = 0; mt < 4; mt++)
#pragma unroll
            for (int i = 0; i < 2; i++)
#pragma unroll
                for (int j = 0; j < 2; j++) {
                    int nn = wn + nt * 16 + (lane >> 2) + i * 8;
                    int mm = wm + mt * 8 + (lane & 3) * 2 + j;
                    sd[mm * EPI_PITCH + nn] = acc[nt][mt][i * 2 + j];
                }
    __syncthreads();

    // deterministic fixup, parallel across warps: warp w owns n-rows [16w, 16w+16)
    for (int nl = wid * 16; nl < wid * 16 + 16; nl++) {
        unsigned long long c64 = cnts[nl];
        if (c64 == 0ull) continue;
#pragma unroll
        for (int seg = 0; seg < OV_SEGS; seg++) {
            int c = (int)((c64 >> (8 * seg)) & 0xFF);
            for (int j = 0; j < c; j++) {
                float2 ev = g_ove[(((size_t)(n0 + nl)) * OV_SEGS + seg) * OV_SLOTS + j];
                int k = __float_as_int(ev.y);
                const __half* xr = g_AT + (size_t)k * Mdim + m0;
#pragma unroll
                for (int q = 0; q < 4; q++) {
                    int m = lane + q * 32;
                    sd[m * EPI_PITCH + nl] += ev.x * __half2float(xr[m]);
                }
            }
        }
    }
    __syncthreads();

#pragma unroll
    for (int i = 0; i < (BMT * BN / 4) / NTHREADS; i++) {  // 16 float4 per thread
        int lin = i * NTHREADS + tid;
        int r = lin >> 5;             // m row (128)
        int c4 = (lin & 31) << 2;     // n col group (32 float4)
        float4 v = *reinterpret_cast<const float4*>(sd + r * EPI_PITCH + c4);
        v.x += bs[c4 + 0]; v.y += bs[c4 + 1]; v.z += bs[c4 + 2]; v.w += bs[c4 + 3];
        *reinterpret_cast<float4*>(out + (size_t)(m0 + r) * Ndim + n0 + c4) = v;
    }
}

// ---------------- launch ----------------

extern "C" void kernel_launch(void* const* d_in, const int* in_sizes, int n_in,
                              void* d_out, int out_size) {
    const float* x = nullptr;
    const float* W = nullptr;
    const float* bias = nullptr;
    for (int i = 0; i < n_in; i++) {
        if (in_sizes[i] == Mdim * Kdim) x = (const float*)d_in[i];
        else if (in_sizes[i] == Kdim * Ndim) W = (const float*)d_in[i];
        else if (in_sizes[i] == Ndim) bias = (const float*)d_in[i];
    }
    float* out = (float*)d_out;

    cudaFuncSetAttribute(gemm_sp_kernel,
                         cudaFuncAttributeMaxDynamicSharedMemorySize, DYN_SMEM);

    conv_x_dual<<<dim3(Kdim / 32, Mdim / 32), dim3(32, 8)>>>(x);
    conv_w_sp<<<dim3(Ndim / 256, Kdim / 32), 256>>>(W);
    conv_w_ov<<<dim3(Ndim / 256, OV_SEGS), 256>>>(W);
    gemm_sp_kernel<<<dim3(Ndim / BN, Mdim / BMT), NTHREADS, DYN_SMEM>>>(bias, out);
}